// round 2
// baseline (speedup 1.0000x reference)
#include <cuda_runtime.h>
#include <cstdint>
#include <math.h>

// Problem constants
#define NUM_E 8
#define M_TOK 2048
#define H_DIM 1024
#define I_DIM 4096

// Intermediate activations: [E, 2048, 4096] fp32 = 256MB static scratch
__device__ float g_act[(size_t)NUM_E * M_TOK * I_DIM];

#define BM 128
#define BN 128
#define BK 16
#define ASTRIDE 20   // (20*r + c) % 32 distinct for r<8, c<4  -> conflict-free A frag LDS
#define BSTRIDE 136  // 136 % 32 == 8 -> (8*k + n) % 32 distinct for k<4, n<8

__device__ __forceinline__ uint32_t cvt_tf32(float f) {
    uint32_t u;
    asm volatile("cvt.rna.tf32.f32 %0, %1;" : "=r"(u) : "f"(f));
    return u;
}

__device__ __forceinline__ void cp_async16(uint32_t smem, const void* gmem) {
    asm volatile("cp.async.cg.shared.global [%0], [%1], 16;\n" :: "r"(smem), "l"(gmem));
}
__device__ __forceinline__ void cp_commit() { asm volatile("cp.async.commit_group;\n" ::: "memory"); }
template <int N> __device__ __forceinline__ void cp_wait() {
    asm volatile("cp.async.wait_group %0;\n" :: "n"(N) : "memory");
}

__device__ __forceinline__ float gelu_exact(float v) {
    // matches jax.nn.gelu(approximate=False): x * 0.5 * (1 + erf(x / sqrt(2)))
    return 0.5f * v * (1.0f + erff(v * 0.70710678118654752440f));
}

// D = A @ B (+ optional exact GELU).
// A: [Mdim, Kdim] row-major per expert, B: [Kdim, Ndim] row-major per expert.
// A_FROM_SCRATCH: read A from g_act; D_TO_SCRATCH: write D to g_act.
template <bool GELU, bool A_FROM_SCRATCH, bool D_TO_SCRATCH>
__global__ void __launch_bounds__(256, 2) gemm_tf32_kernel(
    const float* __restrict__ Ag, const float* __restrict__ Bg, float* __restrict__ Dg,
    int Mdim, int Ndim, int Kdim)
{
    __shared__ float sA[2][BM * ASTRIDE];
    __shared__ float sB[2][BK * BSTRIDE];

    const int e = blockIdx.z;
    const float* A = (A_FROM_SCRATCH ? (const float*)g_act : Ag) + (size_t)e * Mdim * Kdim;
    const float* B = Bg + (size_t)e * Kdim * Ndim;
    float*       D = (D_TO_SCRATCH ? (float*)g_act : Dg) + (size_t)e * Mdim * Ndim;

    const int tid = threadIdx.x;
    const int m0 = blockIdx.y * BM;
    const int n0 = blockIdx.x * BN;

    auto load_stage = [&](int s, int k0) {
        // A tile: 128 rows x 16 cols = 512 float4, 2 per thread
        #pragma unroll
        for (int i = 0; i < 2; ++i) {
            int idx = tid + 256 * i;
            int ar = idx >> 2, ac = (idx & 3) << 2;
            uint32_t dst = (uint32_t)__cvta_generic_to_shared(&sA[s][ar * ASTRIDE + ac]);
            cp_async16(dst, A + (size_t)(m0 + ar) * Kdim + k0 + ac);
        }
        // B tile: 16 rows x 128 cols = 512 float4, 2 per thread
        #pragma unroll
        for (int i = 0; i < 2; ++i) {
            int idx = tid + 256 * i;
            int br = idx >> 5, bc = (idx & 31) << 2;
            uint32_t dst = (uint32_t)__cvta_generic_to_shared(&sB[s][br * BSTRIDE + bc]);
            cp_async16(dst, B + (size_t)(k0 + br) * Ndim + n0 + bc);
        }
        cp_commit();
    };

    float acc[4][4][4];
    #pragma unroll
    for (int a = 0; a < 4; a++)
        #pragma unroll
        for (int b = 0; b < 4; b++)
            #pragma unroll
            for (int c = 0; c < 4; c++) acc[a][b][c] = 0.f;

    const int warp = tid >> 5;
    const int lane = tid & 31;
    const int wm = warp >> 2;   // 0..1  -> warp row (64 rows)
    const int wn = warp & 3;    // 0..3  -> warp col (32 cols)
    const int grp = lane >> 2;  // 0..7
    const int qid = lane & 3;   // 0..3

    const int KT = Kdim / BK;
    load_stage(0, 0);

    for (int kt = 0; kt < KT; ++kt) {
        if (kt + 1 < KT) {
            load_stage((kt + 1) & 1, (kt + 1) * BK);
            cp_wait<1>();   // newest group (next stage) may stay pending; current is done
        } else {
            cp_wait<0>();
        }
        __syncthreads();

        const float* cA = sA[kt & 1];
        const float* cB = sB[kt & 1];

        #pragma unroll
        for (int ks = 0; ks < 2; ++ks) {
            const int kk = ks * 8;
            uint32_t af[4][4], bf[4][2];
            #pragma unroll
            for (int mt = 0; mt < 4; ++mt) {
                int r = wm * 64 + mt * 16 + grp;
                af[mt][0] = cvt_tf32(cA[r * ASTRIDE + kk + qid]);
                af[mt][1] = cvt_tf32(cA[(r + 8) * ASTRIDE + kk + qid]);
                af[mt][2] = cvt_tf32(cA[r * ASTRIDE + kk + qid + 4]);
                af[mt][3] = cvt_tf32(cA[(r + 8) * ASTRIDE + kk + qid + 4]);
            }
            #pragma unroll
            for (int nt = 0; nt < 4; ++nt) {
                int cc = wn * 32 + nt * 8 + grp;
                bf[nt][0] = cvt_tf32(cB[(kk + qid) * BSTRIDE + cc]);
                bf[nt][1] = cvt_tf32(cB[(kk + qid + 4) * BSTRIDE + cc]);
            }
            #pragma unroll
            for (int mt = 0; mt < 4; ++mt)
                #pragma unroll
                for (int nt = 0; nt < 4; ++nt) {
                    asm volatile(
                        "mma.sync.aligned.m16n8k8.row.col.f32.tf32.tf32.f32 "
                        "{%0,%1,%2,%3}, {%4,%5,%6,%7}, {%8,%9}, {%0,%1,%2,%3};\n"
                        : "+f"(acc[mt][nt][0]), "+f"(acc[mt][nt][1]),
                          "+f"(acc[mt][nt][2]), "+f"(acc[mt][nt][3])
                        : "r"(af[mt][0]), "r"(af[mt][1]), "r"(af[mt][2]), "r"(af[mt][3]),
                          "r"(bf[nt][0]), "r"(bf[nt][1]));
                }
        }
        __syncthreads();
    }

    // Epilogue: C fragment c0:(grp, 2q) c1:(grp, 2q+1) c2:(grp+8, 2q) c3:(grp+8, 2q+1)
    #pragma unroll
    for (int mt = 0; mt < 4; ++mt) {
        int r = m0 + wm * 64 + mt * 16 + grp;
        #pragma unroll
        for (int nt = 0; nt < 4; ++nt) {
            int c = n0 + wn * 32 + nt * 8 + 2 * qid;
            float v0 = acc[mt][nt][0], v1 = acc[mt][nt][1];
            float v2 = acc[mt][nt][2], v3 = acc[mt][nt][3];
            if (GELU) {
                v0 = gelu_exact(v0); v1 = gelu_exact(v1);
                v2 = gelu_exact(v2); v3 = gelu_exact(v3);
            }
            *(float2*)(&D[(size_t)r * Ndim + c])       = make_float2(v0, v1);
            *(float2*)(&D[(size_t)(r + 8) * Ndim + c]) = make_float2(v2, v3);
        }
    }
}

extern "C" void kernel_launch(void* const* d_in, const int* in_sizes, int n_in,
                              void* d_out, int out_size) {
    const float* x  = (const float*)d_in[0];   // [1, 8, 2048, 1024] == [8, 2048, 1024]
    const float* wi = (const float*)d_in[1];   // [8, 1024, 4096]
    const float* wo = (const float*)d_in[2];   // [8, 4096, 1024]
    float* out = (float*)d_out;                // [1, 8, 2048, 1024]

    dim3 blk(256);
    // GEMM1: act = gelu(x @ wi)   M=2048 N=4096 K=1024
    dim3 g1(I_DIM / BN, M_TOK / BM, NUM_E);
    gemm_tf32_kernel<true, false, true><<<g1, blk>>>(x, wi, nullptr, M_TOK, I_DIM, H_DIM);
    // GEMM2: out = act @ wo       M=2048 N=1024 K=4096
    dim3 g2(H_DIM / BN, M_TOK / BM, NUM_E);
    gemm_tf32_kernel<false, true, false><<<g2, blk>>>(nullptr, wo, out, M_TOK, H_DIM, I_DIM);
}